// round 3
// baseline (speedup 1.0000x reference)
#include <cuda_runtime.h>
#include <cstdint>

// AR(24) rollout: out[b, t, d] for t in [0,168), seeded from x[b, 336-24 .. 335, d].
// One thread handles TWO adjacent d channels using packed fma.rn.f32x2 (FFMA2),
// which ptxas will not auto-fuse from C++ (see SASS_QUICKREF "patterns absent").
//
// Shapes (fixed by the dataset):
//   x: [256, 336, 512] f32, W: [24,1] f32, b: [1] f32, out: [256, 168, 512] f32

#define ORDER 24
#define T_OUT 168
#define D_DIM 512
#define B_DIM 256
#define S_DIM 336
#define HALF_D (D_DIM / 2)

__global__ __launch_bounds__(256, 2)
void ar_ffma2_kernel(const float* __restrict__ x,
                     const float* __restrict__ W,
                     const float* __restrict__ bias,
                     float* __restrict__ out) {
    const int p = blockIdx.x * blockDim.x + threadIdx.x;  // pair index in [0, B*HALF_D)
    const int b = p / HALF_D;
    const int d = (p - b * HALF_D) * 2;

    // --- duplicated-pair coefficients (lo == hi == W[k]) ---
    unsigned long long wk[ORDER];
#pragma unroll
    for (int k = 0; k < ORDER; k++) {
        unsigned int wi = __float_as_uint(__ldg(&W[k]));
        wk[k] = ((unsigned long long)wi << 32) | (unsigned long long)wi;
    }
    unsigned long long bias2;
    {
        unsigned int bi = __float_as_uint(__ldg(bias));
        bias2 = ((unsigned long long)bi << 32) | (unsigned long long)bi;
    }

    // --- seed window from the last ORDER timesteps (coalesced 8B loads) ---
    unsigned long long win[ORDER];
    const float* xp = x + (size_t)b * S_DIM * D_DIM + (size_t)(S_DIM - ORDER) * D_DIM + d;
#pragma unroll
    for (int k = 0; k < ORDER; k++) {
        win[k] = *reinterpret_cast<const unsigned long long*>(xp + (size_t)k * D_DIM);
    }

    float* op = out + (size_t)b * T_OUT * D_DIM + d;

    // 168 = 7 * 24. Inner 24 steps fully unrolled -> circular index (i+k)%24 is
    // compile-time, window stays in fixed registers (no shifting).
#pragma unroll 1
    for (int outer = 0; outer < T_OUT / ORDER; outer++) {
#pragma unroll
        for (int i = 0; i < ORDER; i++) {
            unsigned long long acc = bias2;
#pragma unroll
            for (int k = 0; k < ORDER; k++) {
                asm("fma.rn.f32x2 %0, %1, %2, %0;"
                    : "+l"(acc)
                    : "l"(wk[k]), "l"(win[(i + k) % ORDER]));
            }
            win[i] = acc;  // new value replaces the oldest slot
            *reinterpret_cast<unsigned long long*>(
                op + (size_t)(outer * ORDER + i) * D_DIM) = acc;
        }
    }
}

extern "C" void kernel_launch(void* const* d_in, const int* in_sizes, int n_in,
                              void* d_out, int out_size) {
    const float* x  = (const float*)d_in[0];   // [256, 336, 512]
    const float* W  = (const float*)d_in[1];   // [24, 1]
    const float* bs = (const float*)d_in[2];   // [1]
    float* out = (float*)d_out;                // [256, 168, 512]

    const int n_threads = B_DIM * HALF_D;      // 65536
    const int block = 256;
    ar_ffma2_kernel<<<n_threads / block, block>>>(x, W, bs, out);
}